// round 1
// baseline (speedup 1.0000x reference)
#include <cuda_runtime.h>
#include <cuda_bf16.h>

// ---------------- problem constants ----------------
#define N_EMBD 1024
#define N_HEAD 16
#define DKH    64          // head dim
#define BB     2
#define TT     2048
#define BT     (BB*TT)     // 4096 rows
#define C3     (3*N_EMBD)  // 3072

// scratch (allocation-free: device globals)
__device__ float g_qkv[BT * C3];      // [4096][3072]  q|k|v per row
__device__ float g_att[BT * N_EMBD];  // [4096][1024]  attention output

// ---------------- NT GEMM:  C[M,N] = A[M,K] * B[N,K]^T ----------------
// A row-major [M,K], B row-major [N,K] (torch Linear weight layout), C row-major.
#define BM  128
#define BN  64
#define TKG 16

__global__ __launch_bounds__(256) void gemm_nt(const float* __restrict__ A,
                                               const float* __restrict__ Bm,
                                               float* __restrict__ Cm,
                                               int M, int N, int K)
{
    __shared__ float As[TKG][BM + 2];   // k-major, padded: conflict-free
    __shared__ float Bs[TKG][BN + 2];

    const int tid = threadIdx.x;
    const int tx = tid & 15;            // n sub-index
    const int ty = tid >> 4;            // m sub-index
    const int m0 = blockIdx.y * BM;
    const int n0 = blockIdx.x * BN;

    float acc[8][4];
#pragma unroll
    for (int i = 0; i < 8; i++)
#pragma unroll
        for (int j = 0; j < 4; j++) acc[i][j] = 0.f;

    for (int kt = 0; kt < K; kt += TKG) {
        // load A tile: 128 rows x 16 k = 512 float4
#pragma unroll
        for (int it = 0; it < 2; it++) {
            int l   = tid + it * 256;
            int row = l >> 2;           // 4 float4 per row
            int c4  = l & 3;
            float4 v = *reinterpret_cast<const float4*>(
                A + (size_t)(m0 + row) * K + kt + c4 * 4);
            As[c4 * 4 + 0][row] = v.x;
            As[c4 * 4 + 1][row] = v.y;
            As[c4 * 4 + 2][row] = v.z;
            As[c4 * 4 + 3][row] = v.w;
        }
        // load B tile: 64 rows x 16 k = 256 float4
        {
            int row = tid >> 2;
            int c4  = tid & 3;
            float4 v = *reinterpret_cast<const float4*>(
                Bm + (size_t)(n0 + row) * K + kt + c4 * 4);
            Bs[c4 * 4 + 0][row] = v.x;
            Bs[c4 * 4 + 1][row] = v.y;
            Bs[c4 * 4 + 2][row] = v.z;
            Bs[c4 * 4 + 3][row] = v.w;
        }
        __syncthreads();

#pragma unroll
        for (int kk = 0; kk < TKG; kk++) {
            float a[8], b[4];
#pragma unroll
            for (int i = 0; i < 8; i++) a[i] = As[kk][ty + 16 * i];
#pragma unroll
            for (int j = 0; j < 4; j++) b[j] = Bs[kk][tx + 16 * j];
#pragma unroll
            for (int i = 0; i < 8; i++)
#pragma unroll
                for (int j = 0; j < 4; j++) acc[i][j] += a[i] * b[j];
        }
        __syncthreads();
    }

#pragma unroll
    for (int i = 0; i < 8; i++)
#pragma unroll
        for (int j = 0; j < 4; j++)
            Cm[(size_t)(m0 + ty + 16 * i) * N + n0 + tx + 16 * j] = acc[i][j];
}

// ---------------- causal flash attention (fp32, 64x64 tiles) ----------------
// block: 256 threads handles one (b, h, q-tile of 64 rows)
// smem: Qs,Ks,Vs,Ps each [64][65] + row stats
#define ATT_PAD 65
#define ATT_SMEM_FLOATS (4 * 64 * ATT_PAD + 3 * 64)
#define ATT_SMEM_BYTES  (ATT_SMEM_FLOATS * 4)

__global__ __launch_bounds__(256) void attn_kernel(const float* __restrict__ qkv,
                                                   float* __restrict__ att)
{
    extern __shared__ float sm[];
    float* Qs = sm;                       // [64][65]
    float* Ks = Qs + 64 * ATT_PAD;
    float* Vs = Ks + 64 * ATT_PAD;
    float* Ps = Vs + 64 * ATT_PAD;
    float* m_s    = Ps + 64 * ATT_PAD;    // [64]
    float* l_s    = m_s + 64;
    float* corr_s = l_s + 64;

    const int tid = threadIdx.x;
    const int tx  = tid & 15;
    const int ty  = tid >> 4;
    const int qt  = blockIdx.x;           // 0..31
    const int bh  = blockIdx.y;           // 0..31
    const int b   = bh / N_HEAD;
    const int h   = bh % N_HEAD;

    // load Q tile (pre-scaled by DK^-0.5 = 0.125 exactly)
#pragma unroll
    for (int it = 0; it < 4; it++) {
        int l   = tid + it * 256;
        int row = l >> 4;                 // 16 float4 per row of 64 floats
        int c4  = l & 15;
        float4 v = *reinterpret_cast<const float4*>(
            qkv + (size_t)(b * TT + qt * 64 + row) * C3 + h * DKH + c4 * 4);
        float* dst = Qs + row * ATT_PAD + c4 * 4;
        dst[0] = v.x * 0.125f; dst[1] = v.y * 0.125f;
        dst[2] = v.z * 0.125f; dst[3] = v.w * 0.125f;
    }
    if (tid < 64) { m_s[tid] = -1e30f; l_s[tid] = 0.f; }

    float o[4][4];
#pragma unroll
    for (int i = 0; i < 4; i++)
#pragma unroll
        for (int j = 0; j < 4; j++) o[i][j] = 0.f;

    __syncthreads();

    for (int kt = 0; kt <= qt; kt++) {
        // load K,V tiles
#pragma unroll
        for (int it = 0; it < 4; it++) {
            int l   = tid + it * 256;
            int row = l >> 4;
            int c4  = l & 15;
            size_t base = (size_t)(b * TT + kt * 64 + row) * C3 + h * DKH + c4 * 4;
            float4 kv = *reinterpret_cast<const float4*>(qkv + base + N_EMBD);
            float4 vv = *reinterpret_cast<const float4*>(qkv + base + 2 * N_EMBD);
            float* dk = Ks + row * ATT_PAD + c4 * 4;
            float* dv = Vs + row * ATT_PAD + c4 * 4;
            dk[0] = kv.x; dk[1] = kv.y; dk[2] = kv.z; dk[3] = kv.w;
            dv[0] = vv.x; dv[1] = vv.y; dv[2] = vv.z; dv[3] = vv.w;
        }
        __syncthreads();

        // S = Qs @ Ks^T  (64x64, contraction over DK=64)
        float s[4][4];
#pragma unroll
        for (int i = 0; i < 4; i++)
#pragma unroll
            for (int j = 0; j < 4; j++) s[i][j] = 0.f;
#pragma unroll 8
        for (int kk = 0; kk < DKH; kk++) {
            float a[4], c[4];
#pragma unroll
            for (int i = 0; i < 4; i++) a[i] = Qs[(ty + 16 * i) * ATT_PAD + kk];
#pragma unroll
            for (int j = 0; j < 4; j++) c[j] = Ks[(tx + 16 * j) * ATT_PAD + kk];
#pragma unroll
            for (int i = 0; i < 4; i++)
#pragma unroll
                for (int j = 0; j < 4; j++) s[i][j] += a[i] * c[j];
        }
        // causal mask, write S tile
#pragma unroll
        for (int i = 0; i < 4; i++) {
            int m_g = qt * 64 + ty + 16 * i;
#pragma unroll
            for (int j = 0; j < 4; j++) {
                int n_g = kt * 64 + tx + 16 * j;
                Ps[(ty + 16 * i) * ATT_PAD + tx + 16 * j] =
                    (n_g <= m_g) ? s[i][j] : -1e30f;
            }
        }
        __syncthreads();

        // online softmax over rows: 4 threads per row
        {
            int r   = tid >> 2;
            int sub = tid & 3;
            float* prow = Ps + r * ATT_PAD;
            float mx = -1e30f;
#pragma unroll
            for (int k = 0; k < 16; k++) mx = fmaxf(mx, prow[sub * 16 + k]);
            mx = fmaxf(mx, __shfl_xor_sync(0xffffffffu, mx, 1));
            mx = fmaxf(mx, __shfl_xor_sync(0xffffffffu, mx, 2));
            float m_old = m_s[r];
            float m_new = fmaxf(m_old, mx);
            float corr  = __expf(m_old - m_new);
            float rsum  = 0.f;
#pragma unroll
            for (int k = 0; k < 16; k++) {
                float p = __expf(prow[sub * 16 + k] - m_new);
                prow[sub * 16 + k] = p;
                rsum += p;
            }
            rsum += __shfl_xor_sync(0xffffffffu, rsum, 1);
            rsum += __shfl_xor_sync(0xffffffffu, rsum, 2);
            if (sub == 0) {
                m_s[r]    = m_new;
                corr_s[r] = corr;
                l_s[r]    = l_s[r] * corr + rsum;
            }
        }
        __syncthreads();

        // O = O*corr + P @ V
        float cr[4];
#pragma unroll
        for (int i = 0; i < 4; i++) cr[i] = corr_s[ty + 16 * i];
#pragma unroll
        for (int i = 0; i < 4; i++)
#pragma unroll
            for (int j = 0; j < 4; j++) o[i][j] *= cr[i];
#pragma unroll 8
        for (int kk = 0; kk < 64; kk++) {
            float p[4], v[4];
#pragma unroll
            for (int i = 0; i < 4; i++) p[i] = Ps[(ty + 16 * i) * ATT_PAD + kk];
#pragma unroll
            for (int j = 0; j < 4; j++) v[j] = Vs[kk * ATT_PAD + tx + 16 * j];
#pragma unroll
            for (int i = 0; i < 4; i++)
#pragma unroll
                for (int j = 0; j < 4; j++) o[i][j] += p[i] * v[j];
        }
        __syncthreads();   // protect Ks/Vs/Ps for next iteration
    }

    // epilogue: normalize and store [b,t,c] with c = h*64 + d
    float inv[4];
#pragma unroll
    for (int i = 0; i < 4; i++) inv[i] = 1.f / l_s[ty + 16 * i];
#pragma unroll
    for (int i = 0; i < 4; i++) {
        size_t row = (size_t)(b * TT + qt * 64 + ty + 16 * i);
#pragma unroll
        for (int j = 0; j < 4; j++)
            att[row * N_EMBD + h * DKH + tx + 16 * j] = o[i][j] * inv[i];
    }
}

// ---------------- launch ----------------
extern "C" void kernel_launch(void* const* d_in, const int* in_sizes, int n_in,
                              void* d_out, int out_size)
{
    const float* x  = (const float*)d_in[0];   // [2,2048,1024]
    const float* wa = (const float*)d_in[1];   // [3072,1024]
    const float* wp = (const float*)d_in[2];   // [1024,1024]
    float* out = (float*)d_out;                // [2,2048,1024]

    float* qkv_ptr = nullptr;
    float* att_ptr = nullptr;
    cudaGetSymbolAddress((void**)&qkv_ptr, g_qkv);
    cudaGetSymbolAddress((void**)&att_ptr, g_att);

    cudaFuncSetAttribute(attn_kernel,
                         cudaFuncAttributeMaxDynamicSharedMemorySize,
                         ATT_SMEM_BYTES);

    // 1) fused QKV projection: [4096,3072] = x[4096,1024] @ w_attn^T
    gemm_nt<<<dim3(C3 / BN, BT / BM), 256>>>(x, wa, qkv_ptr, BT, C3, N_EMBD);

    // 2) causal attention per (b,h,q-tile)
    attn_kernel<<<dim3(TT / 64, BB * N_HEAD), 256, ATT_SMEM_BYTES>>>(qkv_ptr, att_ptr);

    // 3) output projection: [4096,1024] = att @ w_proj^T
    gemm_nt<<<dim3(N_EMBD / BN, BT / BM), 256>>>(att_ptr, wp, out, BT, N_EMBD, N_EMBD);
}

// round 3
// speedup vs baseline: 1.8980x; 1.8980x over previous
#include <cuda_runtime.h>
#include <cstdint>

// ---------------- problem constants ----------------
#define N_EMBD 1024
#define N_HEAD 16
#define DKH    64
#define BB     2
#define TT     2048
#define BT     (BB*TT)     // 4096 rows
#define C3     (3*N_EMBD)  // 3072

// scratch (allocation-free: device globals)
__device__ float g_qkv[BT * C3];      // [4096][3072]
__device__ float g_att[BT * N_EMBD];  // [4096][1024]

// ---------------- tf32 helpers ----------------
__device__ __forceinline__ void mma_tf32(float d[4], const uint32_t a[4], const uint32_t b[2]) {
    asm volatile(
        "mma.sync.aligned.m16n8k8.row.col.f32.tf32.tf32.f32 "
        "{%0,%1,%2,%3}, {%4,%5,%6,%7}, {%8,%9}, {%0,%1,%2,%3};\n"
        : "+f"(d[0]), "+f"(d[1]), "+f"(d[2]), "+f"(d[3])
        : "r"(a[0]), "r"(a[1]), "r"(a[2]), "r"(a[3]),
          "r"(b[0]), "r"(b[1]));
}

// split fp32 into tf32 hi (truncated) + tf32 lo (residual)
__device__ __forceinline__ void split_tf32(float f, uint32_t& hi, uint32_t& lo) {
    uint32_t h = __float_as_uint(f) & 0xFFFFE000u;
    hi = h;
    lo = __float_as_uint(f - __uint_as_float(h));
}

__device__ __forceinline__ uint32_t f2tf32(float f) {
    uint32_t u;
    asm("cvt.rna.tf32.f32 %0, %1;" : "=r"(u) : "f"(f));
    return u;
}

// ---------------- NT GEMM (tensor core, 3-term split-tf32) ----------------
// C[M,N] = A[M,K] * B[N,K]^T ; A,B,C row-major fp32.
#define GBM 128
#define GBN 64
#define GBK 32
#define GPAD 36

__global__ __launch_bounds__(256) void gemm_nt_tc(const float* __restrict__ A,
                                                  const float* __restrict__ Bm,
                                                  float* __restrict__ Cm,
                                                  int M, int N, int K)
{
    __shared__ float As[GBM][GPAD];
    __shared__ float Bs[GBN][GPAD];

    const int tid  = threadIdx.x;
    const int wid  = tid >> 5, lane = tid & 31;
    const int wm   = wid & 3,  wn   = wid >> 2;   // 4x2 warp grid, warp tile 32x32
    const int r    = lane >> 2, tg  = lane & 3;
    const int m0   = blockIdx.y * GBM;
    const int n0   = blockIdx.x * GBN;

    float acc[2][4][4] = {};

    for (int kt = 0; kt < K; kt += GBK) {
        // stage A tile: 128x32 = 1024 float4
#pragma unroll
        for (int it = 0; it < 4; it++) {
            int l = tid + it * 256;
            int row = l >> 3, c4 = l & 7;
            float4 v = *reinterpret_cast<const float4*>(
                A + (size_t)(m0 + row) * K + kt + c4 * 4);
            *reinterpret_cast<float4*>(&As[row][c4 * 4]) = v;
        }
        // stage B tile: 64x32 = 512 float4
#pragma unroll
        for (int it = 0; it < 2; it++) {
            int l = tid + it * 256;
            int row = l >> 3, c4 = l & 7;
            float4 v = *reinterpret_cast<const float4*>(
                Bm + (size_t)(n0 + row) * K + kt + c4 * 4);
            *reinterpret_cast<float4*>(&Bs[row][c4 * 4]) = v;
        }
        __syncthreads();

#pragma unroll
        for (int ks = 0; ks < GBK; ks += 8) {
            uint32_t ah[2][4], al[2][4];
#pragma unroll
            for (int i = 0; i < 2; i++) {
                int mr = wm * 32 + i * 16 + r;
                split_tf32(As[mr][ks + tg],         ah[i][0], al[i][0]);
                split_tf32(As[mr + 8][ks + tg],     ah[i][1], al[i][1]);
                split_tf32(As[mr][ks + tg + 4],     ah[i][2], al[i][2]);
                split_tf32(As[mr + 8][ks + tg + 4], ah[i][3], al[i][3]);
            }
#pragma unroll
            for (int j = 0; j < 4; j++) {
                int nr = wn * 32 + j * 8 + r;
                uint32_t bh[2], bl[2];
                split_tf32(Bs[nr][ks + tg],     bh[0], bl[0]);
                split_tf32(Bs[nr][ks + tg + 4], bh[1], bl[1]);
#pragma unroll
                for (int i = 0; i < 2; i++) {
                    mma_tf32(acc[i][j], ah[i], bh);
                    mma_tf32(acc[i][j], ah[i], bl);
                    mma_tf32(acc[i][j], al[i], bh);
                }
            }
        }
        __syncthreads();
    }

#pragma unroll
    for (int i = 0; i < 2; i++) {
        size_t row0 = (size_t)(m0 + wm * 32 + i * 16 + r);
#pragma unroll
        for (int j = 0; j < 4; j++) {
            int col = n0 + wn * 32 + j * 8 + 2 * tg;
            *reinterpret_cast<float2*>(Cm + row0 * N + col) =
                make_float2(acc[i][j][0], acc[i][j][1]);
            *reinterpret_cast<float2*>(Cm + (row0 + 8) * N + col) =
                make_float2(acc[i][j][2], acc[i][j][3]);
        }
    }
}

// ---------------- causal flash attention (tensor core) ----------------
#define APAD 72
#define ATT_SMEM_FLOATS (4 * 64 * APAD + 3 * 64)
#define ATT_SMEM_BYTES  (ATT_SMEM_FLOATS * 4)

__global__ __launch_bounds__(256) void attn_tc(const float* __restrict__ qkv,
                                               float* __restrict__ att)
{
    extern __shared__ float sm[];
    float (*Qs)[APAD] = reinterpret_cast<float(*)[APAD]>(sm);
    float (*Ks)[APAD] = reinterpret_cast<float(*)[APAD]>(sm + 64 * APAD);
    float (*Vs)[APAD] = reinterpret_cast<float(*)[APAD]>(sm + 2 * 64 * APAD);
    float (*Ps)[APAD] = reinterpret_cast<float(*)[APAD]>(sm + 3 * 64 * APAD);
    float* m_s    = sm + 4 * 64 * APAD;
    float* l_s    = m_s + 64;
    float* corr_s = l_s + 64;

    const int tid  = threadIdx.x;
    const int wid  = tid >> 5, lane = tid & 31;
    const int wm   = wid & 3,  wn   = wid >> 2;   // warp S-tile: rows wm*16..+16, cols wn*32..+32
    const int r    = lane >> 2, tg  = lane & 3;
    const int qt   = blockIdx.x;
    const int bh   = blockIdx.y;
    const int b    = bh >> 4, h = bh & 15;

    // load Q tile (pre-scaled by DK^-0.5 = 0.125)
#pragma unroll
    for (int it = 0; it < 4; it++) {
        int l = tid + it * 256;
        int row = l >> 4, c4 = l & 15;
        float4 v = *reinterpret_cast<const float4*>(
            qkv + (size_t)(b * TT + qt * 64 + row) * C3 + h * DKH + c4 * 4);
        float* dst = &Qs[row][c4 * 4];
        dst[0] = v.x * 0.125f; dst[1] = v.y * 0.125f;
        dst[2] = v.z * 0.125f; dst[3] = v.w * 0.125f;
    }
    if (tid < 64) { m_s[tid] = -1e30f; l_s[tid] = 0.f; }

    float oacc[4][4] = {};
    __syncthreads();

    for (int kt = 0; kt <= qt; kt++) {
        // stage K,V tiles
#pragma unroll
        for (int it = 0; it < 4; it++) {
            int l = tid + it * 256;
            int row = l >> 4, c4 = l & 15;
            size_t base = (size_t)(b * TT + kt * 64 + row) * C3 + h * DKH + c4 * 4;
            float4 kv = *reinterpret_cast<const float4*>(qkv + base + N_EMBD);
            float4 vv = *reinterpret_cast<const float4*>(qkv + base + 2 * N_EMBD);
            *reinterpret_cast<float4*>(&Ks[row][c4 * 4]) = kv;
            *reinterpret_cast<float4*>(&Vs[row][c4 * 4]) = vv;
        }
        __syncthreads();

        // S = Q K^T (3-term split-tf32)
        float sacc[4][4] = {};
#pragma unroll
        for (int ks = 0; ks < DKH; ks += 8) {
            uint32_t ah[4], al[4];
            int mr = wm * 16 + r;
            split_tf32(Qs[mr][ks + tg],         ah[0], al[0]);
            split_tf32(Qs[mr + 8][ks + tg],     ah[1], al[1]);
            split_tf32(Qs[mr][ks + tg + 4],     ah[2], al[2]);
            split_tf32(Qs[mr + 8][ks + tg + 4], ah[3], al[3]);
#pragma unroll
            for (int j = 0; j < 4; j++) {
                int nr = wn * 32 + j * 8 + r;
                uint32_t bh2[2], bl2[2];
                split_tf32(Ks[nr][ks + tg],     bh2[0], bl2[0]);
                split_tf32(Ks[nr][ks + tg + 4], bh2[1], bl2[1]);
                mma_tf32(sacc[j], ah, bh2);
                mma_tf32(sacc[j], ah, bl2);
                mma_tf32(sacc[j], al, bh2);
            }
        }

        // causal mask + write S tile
        {
            int mg0 = qt * 64 + wm * 16 + r;
#pragma unroll
            for (int j = 0; j < 4; j++) {
                int col = wn * 32 + j * 8 + 2 * tg;
                int ng = kt * 64 + col;
                float2 v0, v1;
                v0.x = (ng     <= mg0)     ? sacc[j][0] : -1e30f;
                v0.y = (ng + 1 <= mg0)     ? sacc[j][1] : -1e30f;
                v1.x = (ng     <= mg0 + 8) ? sacc[j][2] : -1e30f;
                v1.y = (ng + 1 <= mg0 + 8) ? sacc[j][3] : -1e30f;
                *reinterpret_cast<float2*>(&Ps[wm * 16 + r][col])     = v0;
                *reinterpret_cast<float2*>(&Ps[wm * 16 + r + 8][col]) = v1;
            }
        }
        __syncthreads();

        // online softmax: 4 threads per row
        {
            int rr = tid >> 2, sub = tid & 3;
            float* prow = Ps[rr];
            float mx = -1e30f;
#pragma unroll
            for (int k = 0; k < 16; k++) mx = fmaxf(mx, prow[sub * 16 + k]);
            mx = fmaxf(mx, __shfl_xor_sync(0xffffffffu, mx, 1));
            mx = fmaxf(mx, __shfl_xor_sync(0xffffffffu, mx, 2));
            float m_old = m_s[rr];
            float m_new = fmaxf(m_old, mx);
            float corr  = __expf(m_old - m_new);
            float rsum  = 0.f;
#pragma unroll
            for (int k = 0; k < 16; k++) {
                float p = __expf(prow[sub * 16 + k] - m_new);
                prow[sub * 16 + k] = p;
                rsum += p;
            }
            rsum += __shfl_xor_sync(0xffffffffu, rsum, 1);
            rsum += __shfl_xor_sync(0xffffffffu, rsum, 2);
            if (sub == 0) {
                m_s[rr]    = m_new;
                corr_s[rr] = corr;
                l_s[rr]    = l_s[rr] * corr + rsum;
            }
        }
        __syncthreads();

        // O = O*corr + P @ V  (P single tf32, V 2-term split)
        {
            float cr0 = corr_s[wm * 16 + r];
            float cr1 = corr_s[wm * 16 + r + 8];
#pragma unroll
            for (int j = 0; j < 4; j++) {
                oacc[j][0] *= cr0; oacc[j][1] *= cr0;
                oacc[j][2] *= cr1; oacc[j][3] *= cr1;
            }
#pragma unroll
            for (int ks = 0; ks < 64; ks += 8) {
                uint32_t pa[4];
                int mr = wm * 16 + r;
                pa[0] = f2tf32(Ps[mr][ks + tg]);
                pa[1] = f2tf32(Ps[mr + 8][ks + tg]);
                pa[2] = f2tf32(Ps[mr][ks + tg + 4]);
                pa[3] = f2tf32(Ps[mr + 8][ks + tg + 4]);
#pragma unroll
                for (int j = 0; j < 4; j++) {
                    int col = wn * 32 + j * 8 + r;
                    uint32_t vh[2], vl[2];
                    split_tf32(Vs[ks + tg][col],     vh[0], vl[0]);
                    split_tf32(Vs[ks + tg + 4][col], vh[1], vl[1]);
                    mma_tf32(oacc[j], pa, vh);
                    mma_tf32(oacc[j], pa, vl);
                }
            }
        }
        __syncthreads();   // protect Ks/Vs/Ps for next iteration
    }

    // epilogue: normalize, store [b,t,c], c = h*64 + d
    {
        float inv0 = 1.f / l_s[wm * 16 + r];
        float inv1 = 1.f / l_s[wm * 16 + r + 8];
        size_t row0 = (size_t)(b * TT + qt * 64 + wm * 16 + r);
#pragma unroll
        for (int j = 0; j < 4; j++) {
            int col = h * DKH + wn * 32 + j * 8 + 2 * tg;
            *reinterpret_cast<float2*>(att + row0 * N_EMBD + col) =
                make_float2(oacc[j][0] * inv0, oacc[j][1] * inv0);
            *reinterpret_cast<float2*>(att + (row0 + 8) * N_EMBD + col) =
                make_float2(oacc[j][2] * inv1, oacc[j][3] * inv1);
        }
    }
}

// ---------------- launch ----------------
extern "C" void kernel_launch(void* const* d_in, const int* in_sizes, int n_in,
                              void* d_out, int out_size)
{
    const float* x  = (const float*)d_in[0];   // [2,2048,1024]
    const float* wa = (const float*)d_in[1];   // [3072,1024]
    const float* wp = (const float*)d_in[2];   // [1024,1024]
    float* out = (float*)d_out;                // [2,2048,1024]

    float* qkv_ptr = nullptr;
    float* att_ptr = nullptr;
    cudaGetSymbolAddress((void**)&qkv_ptr, g_qkv);
    cudaGetSymbolAddress((void**)&att_ptr, g_att);

    cudaFuncSetAttribute(attn_tc,
                         cudaFuncAttributeMaxDynamicSharedMemorySize,
                         ATT_SMEM_BYTES);

    // 1) fused QKV projection
    gemm_nt_tc<<<dim3(C3 / GBN, BT / GBM), 256>>>(x, wa, qkv_ptr, BT, C3, N_EMBD);

    // 2) causal attention
    attn_tc<<<dim3(TT / 64, BB * N_HEAD), 256, ATT_SMEM_BYTES>>>(qkv_ptr, att_ptr);

    // 3) output projection
    gemm_nt_tc<<<dim3(N_EMBD / GBN, BT / GBM), 256>>>(att_ptr, wp, out, BT, N_EMBD, N_EMBD);
}

// round 4
// speedup vs baseline: 2.4854x; 1.3095x over previous
#include <cuda_runtime.h>
#include <cuda_bf16.h>
#include <cstdint>

// ---------------- problem constants ----------------
#define N_EMBD 1024
#define N_HEAD 16
#define DKH    64
#define BB     2
#define TT     2048
#define BT     (BB*TT)     // 4096 rows
#define C3     (3*N_EMBD)  // 3072

// scratch (allocation-free: device globals)
__device__ float g_qkv[BT * C3];      // [4096][3072]
__device__ float g_att[BT * N_EMBD];  // [4096][1024]

// ---------------- bf16 helpers ----------------
__device__ __forceinline__ uint32_t packbf(__nv_bfloat16 a, __nv_bfloat16 b) {
    return (uint32_t)__bfloat16_as_ushort(a) | ((uint32_t)__bfloat16_as_ushort(b) << 16);
}

// split two fp32 into packed bf16 hi pair + bf16 residual-lo pair (a in low half)
__device__ __forceinline__ void split2(float f0, float f1, uint32_t& hi, uint32_t& lo) {
    __nv_bfloat16 h0 = __float2bfloat16_rn(f0);
    __nv_bfloat16 h1 = __float2bfloat16_rn(f1);
    float r0 = f0 - __bfloat162float(h0);
    float r1 = f1 - __bfloat162float(h1);
    hi = packbf(h0, h1);
    lo = packbf(__float2bfloat16_rn(r0), __float2bfloat16_rn(r1));
}

__device__ __forceinline__ void mma_bf16(float d[4], const uint32_t a[4], const uint32_t b[2]) {
    asm volatile(
        "mma.sync.aligned.m16n8k16.row.col.f32.bf16.bf16.f32 "
        "{%0,%1,%2,%3}, {%4,%5,%6,%7}, {%8,%9}, {%0,%1,%2,%3};\n"
        : "+f"(d[0]), "+f"(d[1]), "+f"(d[2]), "+f"(d[3])
        : "r"(a[0]), "r"(a[1]), "r"(a[2]), "r"(a[3]),
          "r"(b[0]), "r"(b[1]));
}

__device__ __forceinline__ void ldm_x2_t(uint32_t& r0, uint32_t& r1, uint32_t addr) {
    asm volatile("ldmatrix.sync.aligned.m8n8.x2.trans.shared.b16 {%0,%1}, [%2];"
                 : "=r"(r0), "=r"(r1) : "r"(addr));
}

// ---------------- NT GEMM (bf16 3-term split, pre-split smem) ----------------
// C[M,N] = A[M,K] * B[N,K]^T ; A,B,C row-major fp32.
#define GBM 128
#define GBN 64
#define GBK 32
#define GKP 20   // GBK/2 + 4 pad (u32 per row)

__global__ __launch_bounds__(256) void gemm_nt_bf16(const float* __restrict__ A,
                                                    const float* __restrict__ Bm,
                                                    float* __restrict__ Cm,
                                                    int M, int N, int K)
{
    __shared__ uint32_t Ah[GBM][GKP], Al[GBM][GKP];
    __shared__ uint32_t Bh[GBN][GKP], Bl[GBN][GKP];

    const int tid  = threadIdx.x;
    const int wid  = tid >> 5, lane = tid & 31;
    const int wm   = wid & 3,  wn   = wid >> 2;   // 4x2 warp grid, warp tile 32x32
    const int r    = lane >> 2, tg  = lane & 3;
    const int m0   = blockIdx.y * GBM;
    const int n0   = blockIdx.x * GBN;

    float acc[2][4][4] = {};

    for (int kt = 0; kt < K; kt += GBK) {
        // stage+split A tile: 128x32 floats
#pragma unroll
        for (int it = 0; it < 4; it++) {
            int l = tid + it * 256;
            int row = l >> 3, c4 = l & 7;
            float4 v = *reinterpret_cast<const float4*>(
                A + (size_t)(m0 + row) * K + kt + c4 * 4);
            split2(v.x, v.y, Ah[row][c4 * 2],     Al[row][c4 * 2]);
            split2(v.z, v.w, Ah[row][c4 * 2 + 1], Al[row][c4 * 2 + 1]);
        }
        // stage+split B tile: 64x32 floats
#pragma unroll
        for (int it = 0; it < 2; it++) {
            int l = tid + it * 256;
            int row = l >> 3, c4 = l & 7;
            float4 v = *reinterpret_cast<const float4*>(
                Bm + (size_t)(n0 + row) * K + kt + c4 * 4);
            split2(v.x, v.y, Bh[row][c4 * 2],     Bl[row][c4 * 2]);
            split2(v.z, v.w, Bh[row][c4 * 2 + 1], Bl[row][c4 * 2 + 1]);
        }
        __syncthreads();

#pragma unroll
        for (int kb = 0; kb < GBK / 2; kb += 8) {   // kb = k16 step in u32 units
            uint32_t ah[2][4], al[2][4];
#pragma unroll
            for (int i = 0; i < 2; i++) {
                int mr = wm * 32 + i * 16 + r;
                ah[i][0] = Ah[mr][kb + tg];         al[i][0] = Al[mr][kb + tg];
                ah[i][1] = Ah[mr + 8][kb + tg];     al[i][1] = Al[mr + 8][kb + tg];
                ah[i][2] = Ah[mr][kb + tg + 4];     al[i][2] = Al[mr][kb + tg + 4];
                ah[i][3] = Ah[mr + 8][kb + tg + 4]; al[i][3] = Al[mr + 8][kb + tg + 4];
            }
#pragma unroll
            for (int j = 0; j < 4; j++) {
                int nr = wn * 32 + j * 8 + r;
                uint32_t bhf[2] = { Bh[nr][kb + tg], Bh[nr][kb + tg + 4] };
                uint32_t blf[2] = { Bl[nr][kb + tg], Bl[nr][kb + tg + 4] };
#pragma unroll
                for (int i = 0; i < 2; i++) {
                    mma_bf16(acc[i][j], ah[i], bhf);
                    mma_bf16(acc[i][j], al[i], bhf);
                    mma_bf16(acc[i][j], ah[i], blf);
                }
            }
        }
        __syncthreads();
    }

#pragma unroll
    for (int i = 0; i < 2; i++) {
        size_t row0 = (size_t)(m0 + wm * 32 + i * 16 + r);
#pragma unroll
        for (int j = 0; j < 4; j++) {
            int col = n0 + wn * 32 + j * 8 + 2 * tg;
            *reinterpret_cast<float2*>(Cm + row0 * N + col) =
                make_float2(acc[i][j][0], acc[i][j][1]);
            *reinterpret_cast<float2*>(Cm + (row0 + 8) * N + col) =
                make_float2(acc[i][j][2], acc[i][j][3]);
        }
    }
}

// ---------------- causal flash attention (bf16 tensor core, reg softmax) ----------------
// smem layout (bytes):
//   Qh 0, Ql 9216, Kh 18432, Kl 27648, Vh 36864, Vl 46080, Ph 55296, Pl 64512,
//   pmax 73728 (2*64 f32), psum 74240 (2*64 f32)  -> total 74752
#define ATT_SMEM_BYTES 74752

__global__ __launch_bounds__(256) void attn_bf16(const float* __restrict__ qkv,
                                                 float* __restrict__ att)
{
    extern __shared__ char smc[];
    uint32_t (*Qh)[36] = (uint32_t(*)[36])(smc);
    uint32_t (*Ql)[36] = (uint32_t(*)[36])(smc + 9216);
    uint32_t (*Kh)[36] = (uint32_t(*)[36])(smc + 18432);
    uint32_t (*Kl)[36] = (uint32_t(*)[36])(smc + 27648);
    __nv_bfloat16 (*Vh)[72] = (__nv_bfloat16(*)[72])(smc + 36864);
    __nv_bfloat16 (*Vl)[72] = (__nv_bfloat16(*)[72])(smc + 46080);
    uint32_t (*Ph)[36] = (uint32_t(*)[36])(smc + 55296);
    uint32_t (*Pl)[36] = (uint32_t(*)[36])(smc + 64512);
    float* pmax = (float*)(smc + 73728);   // [2][64]
    float* psum = (float*)(smc + 74240);   // [2][64]

    const int tid  = threadIdx.x;
    const int wid  = tid >> 5, lane = tid & 31;
    const int wm   = wid & 3,  wn   = wid >> 2;   // warp S-tile rows wm*16..+16, cols wn*32..+32
    const int r    = lane >> 2, tg  = lane & 3;
    const int qt   = blockIdx.x;
    const int bh_  = blockIdx.y;
    const int b    = bh_ >> 4, h = bh_ & 15;

    const uint32_t vh_base = (uint32_t)__cvta_generic_to_shared(Vh);
    const uint32_t vl_base = (uint32_t)__cvta_generic_to_shared(Vl);

    // stage Q (pre-scaled by DK^-0.5 = 0.125), split to bf16 hi/lo pairs along k
#pragma unroll
    for (int it = 0; it < 4; it++) {
        int l = tid + it * 256;
        int row = l >> 4, c4 = l & 15;
        float4 v = *reinterpret_cast<const float4*>(
            qkv + (size_t)(b * TT + qt * 64 + row) * C3 + h * DKH + c4 * 4);
        split2(v.x * 0.125f, v.y * 0.125f, Qh[row][c4 * 2],     Ql[row][c4 * 2]);
        split2(v.z * 0.125f, v.w * 0.125f, Qh[row][c4 * 2 + 1], Ql[row][c4 * 2 + 1]);
    }

    const int mr  = wm * 16 + r;          // local row (0..63), second row mr+8
    float m0_ = -1e30f, m1_ = -1e30f;     // per-row running max (registers)
    float l0_ = 0.f,    l1_ = 0.f;        // per-row running sum (registers)
    float oacc[4][4] = {};

    for (int kt = 0; kt <= qt; kt++) {
        __syncthreads();   // S0: Q staged (first iter) / prev PV reads of K,V,P done

        // stage+split K, V tiles
#pragma unroll
        for (int it = 0; it < 4; it++) {
            int l = tid + it * 256;
            int row = l >> 4, c4 = l & 15;
            size_t base = (size_t)(b * TT + kt * 64 + row) * C3 + h * DKH + c4 * 4;
            float4 kv = *reinterpret_cast<const float4*>(qkv + base + N_EMBD);
            float4 vv = *reinterpret_cast<const float4*>(qkv + base + 2 * N_EMBD);
            split2(kv.x, kv.y, Kh[row][c4 * 2],     Kl[row][c4 * 2]);
            split2(kv.z, kv.w, Kh[row][c4 * 2 + 1], Kl[row][c4 * 2 + 1]);
            uint32_t h01, l01, h23, l23;
            split2(vv.x, vv.y, h01, l01);
            split2(vv.z, vv.w, h23, l23);
            uint32_t* vh32 = reinterpret_cast<uint32_t*>(&Vh[row][c4 * 4]);
            uint32_t* vl32 = reinterpret_cast<uint32_t*>(&Vl[row][c4 * 4]);
            vh32[0] = h01; vh32[1] = h23;
            vl32[0] = l01; vl32[1] = l23;
        }
        __syncthreads();   // S1

        // S = Q K^T (3-term bf16 split)
        float sacc[4][4] = {};
#pragma unroll
        for (int kb = 0; kb < 32; kb += 8) {
            uint32_t ah[4], al[4];
            ah[0] = Qh[mr][kb + tg];         al[0] = Ql[mr][kb + tg];
            ah[1] = Qh[mr + 8][kb + tg];     al[1] = Ql[mr + 8][kb + tg];
            ah[2] = Qh[mr][kb + tg + 4];     al[2] = Ql[mr][kb + tg + 4];
            ah[3] = Qh[mr + 8][kb + tg + 4]; al[3] = Ql[mr + 8][kb + tg + 4];
#pragma unroll
            for (int j = 0; j < 4; j++) {
                int nr = wn * 32 + j * 8 + r;
                uint32_t bhf[2] = { Kh[nr][kb + tg], Kh[nr][kb + tg + 4] };
                uint32_t blf[2] = { Kl[nr][kb + tg], Kl[nr][kb + tg + 4] };
                mma_bf16(sacc[j], ah, bhf);
                mma_bf16(sacc[j], al, bhf);
                mma_bf16(sacc[j], ah, blf);
            }
        }

        // mask + per-row max (warp partial)
        const int mg0 = qt * 64 + mr;
        float mx0 = -1e30f, mx1 = -1e30f;
#pragma unroll
        for (int j = 0; j < 4; j++) {
            int ng = kt * 64 + wn * 32 + j * 8 + 2 * tg;
            if (ng     > mg0)     sacc[j][0] = -1e30f;
            if (ng + 1 > mg0)     sacc[j][1] = -1e30f;
            if (ng     > mg0 + 8) sacc[j][2] = -1e30f;
            if (ng + 1 > mg0 + 8) sacc[j][3] = -1e30f;
            mx0 = fmaxf(mx0, fmaxf(sacc[j][0], sacc[j][1]));
            mx1 = fmaxf(mx1, fmaxf(sacc[j][2], sacc[j][3]));
        }
        mx0 = fmaxf(mx0, __shfl_xor_sync(0xffffffffu, mx0, 1));
        mx0 = fmaxf(mx0, __shfl_xor_sync(0xffffffffu, mx0, 2));
        mx1 = fmaxf(mx1, __shfl_xor_sync(0xffffffffu, mx1, 1));
        mx1 = fmaxf(mx1, __shfl_xor_sync(0xffffffffu, mx1, 2));
        if (tg == 0) {
            pmax[wn * 64 + mr]     = mx0;
            pmax[wn * 64 + mr + 8] = mx1;
        }
        __syncthreads();   // S2

        // softmax in registers; write packed bf16 P hi/lo
        float mn0 = fmaxf(m0_, fmaxf(pmax[mr],     pmax[64 + mr]));
        float mn1 = fmaxf(m1_, fmaxf(pmax[mr + 8], pmax[64 + mr + 8]));
        float cr0 = __expf(m0_ - mn0), cr1 = __expf(m1_ - mn1);
        m0_ = mn0; m1_ = mn1;
        float s0 = 0.f, s1 = 0.f;
#pragma unroll
        for (int j = 0; j < 4; j++) {
            float p0 = __expf(sacc[j][0] - mn0), p1 = __expf(sacc[j][1] - mn0);
            float p2 = __expf(sacc[j][2] - mn1), p3 = __expf(sacc[j][3] - mn1);
            s0 += p0 + p1; s1 += p2 + p3;
            int ci = wn * 16 + j * 4 + tg;
            split2(p0, p1, Ph[mr][ci],     Pl[mr][ci]);
            split2(p2, p3, Ph[mr + 8][ci], Pl[mr + 8][ci]);
        }
        s0 += __shfl_xor_sync(0xffffffffu, s0, 1);
        s0 += __shfl_xor_sync(0xffffffffu, s0, 2);
        s1 += __shfl_xor_sync(0xffffffffu, s1, 1);
        s1 += __shfl_xor_sync(0xffffffffu, s1, 2);
        if (tg == 0) {
            psum[wn * 64 + mr]     = s0;
            psum[wn * 64 + mr + 8] = s1;
        }
        __syncthreads();   // S3

        l0_ = l0_ * cr0 + psum[mr]     + psum[64 + mr];
        l1_ = l1_ * cr1 + psum[mr + 8] + psum[64 + mr + 8];
#pragma unroll
        for (int j = 0; j < 4; j++) {
            oacc[j][0] *= cr0; oacc[j][1] *= cr0;
            oacc[j][2] *= cr1; oacc[j][3] *= cr1;
        }

        // O += P @ V (3-term bf16 split; V via ldmatrix.trans)
#pragma unroll
        for (int kb = 0; kb < 32; kb += 8) {
            uint32_t pah[4], pal[4];
            pah[0] = Ph[mr][kb + tg];         pal[0] = Pl[mr][kb + tg];
            pah[1] = Ph[mr + 8][kb + tg];     pal[1] = Pl[mr + 8][kb + tg];
            pah[2] = Ph[mr][kb + tg + 4];     pal[2] = Pl[mr][kb + tg + 4];
            pah[3] = Ph[mr + 8][kb + tg + 4]; pal[3] = Pl[mr + 8][kb + tg + 4];
            int krow = kb * 2 + (lane & 15);
#pragma unroll
            for (int j = 0; j < 4; j++) {
                int c0j = wn * 32 + j * 8;
                uint32_t vh0, vh1, vl0, vl1;
                ldm_x2_t(vh0, vh1, vh_base + krow * 144 + c0j * 2);
                ldm_x2_t(vl0, vl1, vl_base + krow * 144 + c0j * 2);
                uint32_t bhf[2] = { vh0, vh1 };
                uint32_t blf[2] = { vl0, vl1 };
                mma_bf16(oacc[j], pah, bhf);
                mma_bf16(oacc[j], pal, bhf);
                mma_bf16(oacc[j], pah, blf);
            }
        }
    }

    // epilogue: normalize, store [b,t,c], c = h*64 + d
    {
        float inv0 = 1.f / l0_, inv1 = 1.f / l1_;
        size_t row0 = (size_t)(b * TT + qt * 64 + mr);
#pragma unroll
        for (int j = 0; j < 4; j++) {
            int col = h * DKH + wn * 32 + j * 8 + 2 * tg;
            *reinterpret_cast<float2*>(att + row0 * N_EMBD + col) =
                make_float2(oacc[j][0] * inv0, oacc[j][1] * inv0);
            *reinterpret_cast<float2*>(att + (row0 + 8) * N_EMBD + col) =
                make_float2(oacc[j][2] * inv1, oacc[j][3] * inv1);
        }
    }
}

// ---------------- launch ----------------
extern "C" void kernel_launch(void* const* d_in, const int* in_sizes, int n_in,
                              void* d_out, int out_size)
{
    const float* x  = (const float*)d_in[0];   // [2,2048,1024]
    const float* wa = (const float*)d_in[1];   // [3072,1024]
    const float* wp = (const float*)d_in[2];   // [1024,1024]
    float* out = (float*)d_out;                // [2,2048,1024]

    float* qkv_ptr = nullptr;
    float* att_ptr = nullptr;
    cudaGetSymbolAddress((void**)&qkv_ptr, g_qkv);
    cudaGetSymbolAddress((void**)&att_ptr, g_att);

    cudaFuncSetAttribute(attn_bf16,
                         cudaFuncAttributeMaxDynamicSharedMemorySize,
                         ATT_SMEM_BYTES);

    // 1) fused QKV projection
    gemm_nt_bf16<<<dim3(C3 / GBN, BT / GBM), 256>>>(x, wa, qkv_ptr, BT, C3, N_EMBD);

    // 2) causal attention
    attn_bf16<<<dim3(TT / 64, BB * N_HEAD), 256, ATT_SMEM_BYTES>>>(qkv_ptr, att_ptr);

    // 3) output projection
    gemm_nt_bf16<<<dim3(N_EMBD / GBN, BT / GBM), 256>>>(att_ptr, wp, out, BT, N_EMBD, N_EMBD);
}